// round 13
// baseline (speedup 1.0000x reference)
#include <cuda_runtime.h>
#include <stdint.h>
#include <math.h>

#define NF 64
#define NC 51
#define LG 1001
#define NB 16
#define NH 256
#define NW 256
#define GP 262
#define PSIPLANE ((size_t)NB * NH * NW)

// ---------------- scratch ----------------
__device__ float  d_wn [NF * 49];
__device__ float  d_wnf[NF * 49];
__device__ float2 d_tab2[NF * 1000];
__device__ float  d_lut[3];
__device__ float  d_psi[49 * ((size_t)NB * NH * NW)]; // 205 MB
__device__ float  d_g  [NB * GP * GP];

// ---------------- helpers ----------------
__device__ __forceinline__ unsigned cvt_tf32(float v) {
    unsigned u;
    asm("cvt.rna.tf32.f32 %0, %1;" : "=r"(u) : "f"(v));
    return u;
}

__device__ __forceinline__ void mma_tf32(float& c0, float& c1, float& c2, float& c3,
                                         unsigned a0, unsigned a1, unsigned a2, unsigned a3,
                                         unsigned b0, unsigned b1) {
    asm volatile(
        "mma.sync.aligned.m16n8k8.row.col.f32.tf32.tf32.f32 "
        "{%0,%1,%2,%3}, {%4,%5,%6,%7}, {%8,%9}, {%0,%1,%2,%3};"
        : "+f"(c0), "+f"(c1), "+f"(c2), "+f"(c3)
        : "r"(a0), "r"(a1), "r"(a2), "r"(a3), "r"(b0), "r"(b1));
}

// ---------------- prep 1 ----------------
__global__ void prep_weights(const float* __restrict__ cw,
                             const float* __restrict__ sf,
                             const float* __restrict__ grid)
{
    int f = threadIdx.x;
    if (f < NF) {
        float s = 0.f;
        for (int k = 0; k < 49; ++k) s += cw[f * 49 + k];
        float mean = s / 49.0f;
        float ss = 0.f;
        for (int k = 0; k < 49; ++k) {
            float v = cw[f * 49 + k] - mean;
            ss += v * v;
        }
        float sc = sf[f] / sqrtf(ss);
        for (int k = 0; k < 49; ++k) {
            float v = (cw[f * 49 + k] - mean) * sc;
            d_wn[f * 49 + k] = v;
            int p = k / 7, q = k % 7;
            d_wnf[f * 49 + (6 - p) * 7 + (6 - q)] = v;
        }
    }
    if (threadIdx.x == 0) {
        d_lut[0] = grid[0];
        d_lut[1] = grid[LG - 1];
        d_lut[2] = 1.0f / (grid[1] - grid[0]);
    }
}

// ---------------- prep 2 ----------------
__global__ void prep_table(const float* __restrict__ rw,
                           const float* __restrict__ centers,
                           const float* __restrict__ grid)
{
    __shared__ float tl[LG];
    __shared__ float cs[NC];
    __shared__ float rs[NC];
    int f = blockIdx.x;
    int t = threadIdx.x;
    if (t < NC) { cs[t] = centers[t]; rs[t] = rw[f * NC + t]; }
    __syncthreads();
    for (int l = t; l < LG; l += blockDim.x) {
        float g = grid[l];
        float s = 0.f;
        #pragma unroll 1
        for (int c = 0; c < NC; ++c) {
            float dd = 0.25f * (g - cs[c]);
            s += rs[c] * expf(-0.5f * dd * dd);
        }
        tl[l] = s;
    }
    __syncthreads();
    for (int l = t; l < LG - 1; l += blockDim.x)
        d_tab2[f * 1000 + l] = make_float2(tl[l], tl[l + 1]);
}

// ---------------- fused kernel: x -> conv(tf32 mma) -> LUT -> psi GEMM -> psi -----
// Block: 128 threads (4 warps). Tile: 64 px of one row, all 64 filters.
// Warp w owns m-tile rows [16w, 16w+16).
// smem: phis [64f][72] (raw fp32 bits of phi); reg2 = union(patch+ws | sb).
#define PST 72
__global__ void __launch_bounds__(128) fused_kernel(const float* __restrict__ x)
{
    __shared__ unsigned phis[64 * PST];       // 18.4 KB
    __shared__ float    reg2[4088];           // 16.3 KB: patch[0,504) + ws[504,4088); sb overlays

    int b  = blockIdx.z;
    int y0 = blockIdx.y;
    int x0 = blockIdx.x * 64;
    int tid = threadIdx.x;

    float*    patch = reg2;                   // 7 rows x 70 cols, stride 72
    unsigned* ws    = (unsigned*)(reg2 + 504); // [k][f], 56 x 64, tf32

    const float* xb = x + ((size_t)b << 16);

    // patch with symmetric padding
    for (int t = tid; t < 7 * 70; t += 128) {
        int r = t / 70, c = t - r * 70;
        int gi = y0 - 3 + r;
        int gj = x0 - 3 + c;
        gi = (gi < 0) ? (-1 - gi) : ((gi >= NH) ? (2 * NH - 1 - gi) : gi);
        gj = (gj < 0) ? (-1 - gj) : ((gj >= NW) ? (2 * NW - 1 - gj) : gj);
        patch[r * PST + c] = xb[(gi << 8) + gj];
    }
    // forward weights [k][f], zero rows k>=49
    for (int t = tid; t < 56 * 64; t += 128) {
        int k = t >> 6, f = t & 63;
        ws[t] = (k < 49) ? cvt_tf32(d_wn[f * 49 + k]) : 0u;
    }
    __syncthreads();

    float g0 = d_lut[0], gmax = d_lut[1], invstep = d_lut[2];

    int lane = tid & 31, wrp = tid >> 5;
    int lam = lane & 3;
    int grp = lane >> 2;
    int mrow = wrp * 16;

    // A offsets for fwd GEMM: col c -> patch[c/7][px + c%7]
    int offA[7][2];
    #pragma unroll
    for (int kk = 0; kk < 7; ++kk) {
        #pragma unroll
        for (int h = 0; h < 2; ++h) {
            int c = kk * 8 + lam + 4 * h;
            if (c > 48) c = 48;
            offA[kk][h] = (c / 7) * PST + (c % 7);
        }
    }

    // ---- stage 1: forward conv + LUT -> phis (2 filter chunks of 32) ----
    #pragma unroll 1
    for (int fc = 0; fc < 2; ++fc) {
        unsigned bfr[4][7][2];
        #pragma unroll
        for (int n = 0; n < 4; ++n)
            #pragma unroll
            for (int kk = 0; kk < 7; ++kk) {
                bfr[n][kk][0] = ws[(kk * 8 + lam)     * 64 + fc * 32 + n * 8 + grp];
                bfr[n][kk][1] = ws[(kk * 8 + lam + 4) * 64 + fc * 32 + n * 8 + grp];
            }

        float acc[4][4];
        #pragma unroll
        for (int n = 0; n < 4; ++n)
            #pragma unroll
            for (int j = 0; j < 4; ++j) acc[n][j] = 0.f;

        const float* pb = patch + mrow + grp;
        #pragma unroll
        for (int kk = 0; kk < 7; ++kk) {
            unsigned a0 = __float_as_uint(pb[offA[kk][0]]);
            unsigned a1 = __float_as_uint(pb[offA[kk][0] + 8]);
            unsigned a2 = __float_as_uint(pb[offA[kk][1]]);
            unsigned a3 = __float_as_uint(pb[offA[kk][1] + 8]);
            #pragma unroll
            for (int n = 0; n < 4; ++n)
                mma_tf32(acc[n][0], acc[n][1], acc[n][2], acc[n][3],
                         a0, a1, a2, a3, bfr[n][kk][0], bfr[n][kk][1]);
        }

        // LUT -> phis[f][px] (raw fp32 bits; tf32 truncation happens in MMA)
        #pragma unroll
        for (int n = 0; n < 4; ++n) {
            #pragma unroll
            for (int j = 0; j < 4; ++j) {
                int f  = fc * 32 + n * 8 + 2 * lam + (j & 1);
                int px = mrow + grp + 8 * (j >> 1);
                float v = fminf(fmaxf(acc[n][j], g0), gmax);
                float pos = (v - g0) * invstep;
                int idx = (int)floorf(pos);
                idx = idx < 0 ? 0 : (idx > 999 ? 999 : idx);
                float fr = pos - (float)idx;
                float2 tv = __ldg(d_tab2 + f * 1000 + idx);
                phis[f * PST + px] = __float_as_uint(tv.x * (1.0f - fr) + tv.y * fr);
            }
        }
    }
    __syncthreads();

    // ---- stage 2: overlay adjoint weights sb[f][uv] ----
    unsigned* sb = (unsigned*)reg2;           // 64 x 57
    for (int t = tid; t < 64 * 57; t += 128) {
        int f = t / 57, uv = t - f * 57;
        sb[t] = (uv < 49) ? cvt_tf32(d_wnf[f * 49 + uv]) : 0u;
    }
    __syncthreads();

    // ---- stage 3: psi GEMM  psi[px][uv] = sum_f phi[px][f] * wnf[f][uv] ----
    float acc2[7][4];
    #pragma unroll
    for (int n = 0; n < 7; ++n)
        #pragma unroll
        for (int j = 0; j < 4; ++j) acc2[n][j] = 0.f;

    #pragma unroll
    for (int kk = 0; kk < 8; ++kk) {
        unsigned bf[7][2];
        #pragma unroll
        for (int n = 0; n < 7; ++n) {
            bf[n][0] = sb[(kk * 8 + lam)     * 57 + n * 8 + grp];
            bf[n][1] = sb[(kk * 8 + lam + 4) * 57 + n * 8 + grp];
        }
        unsigned a0 = phis[(kk * 8 + lam)     * PST + mrow + grp];
        unsigned a1 = phis[(kk * 8 + lam)     * PST + mrow + grp + 8];
        unsigned a2 = phis[(kk * 8 + lam + 4) * PST + mrow + grp];
        unsigned a3 = phis[(kk * 8 + lam + 4) * PST + mrow + grp + 8];
        #pragma unroll
        for (int n = 0; n < 7; ++n)
            mma_tf32(acc2[n][0], acc2[n][1], acc2[n][2], acc2[n][3],
                     a0, a1, a2, a3, bf[n][0], bf[n][1]);
    }

    // ---- store psi ----
    size_t bpx = ((size_t)b << 16) + ((size_t)y0 << 8) + x0;
    #pragma unroll
    for (int n = 0; n < 7; ++n) {
        #pragma unroll
        for (int j = 0; j < 4; ++j) {
            int uv = n * 8 + 2 * lam + (j & 1);
            if (uv < 49) {
                int pl = mrow + grp + 8 * (j >> 1);
                d_psi[(size_t)uv * PSIPLANE + bpx + pl] = acc2[n][j];
            }
        }
    }
}

// ---------------- fold: g[m,n] = sum_uv psi[uv][m-6+u][n-6+v] ----------------
__global__ void __launch_bounds__(256) fold_kernel()
{
    int t = blockIdx.x * 256 + threadIdx.x;
    if (t >= GP * GP) return;
    int b = blockIdx.y;
    int m = t / GP;
    int n = t - m * GP;

    float acc = 0.f;
    #pragma unroll
    for (int u = 0; u < 7; ++u) {
        int y = m - 6 + u;
        if ((unsigned)y < (unsigned)NH) {
            const float* base = d_psi + (size_t)(u * 7) * PSIPLANE
                              + ((size_t)b << 16) + (y << 8);
            #pragma unroll
            for (int v = 0; v < 7; ++v) {
                int xx = n - 6 + v;
                if ((unsigned)xx < (unsigned)NW)
                    acc += base[(size_t)v * PSIPLANE + xx];
            }
        }
    }
    d_g[(size_t)b * GP * GP + t] = acc;
}

// ---------------- finish: fold borders + residual + prox ----------------
__global__ void finish_kernel(const float* __restrict__ input,
                              const float* __restrict__ noisy,
                              const float* __restrict__ a_cond,
                              float* __restrict__ out)
{
    int t = blockIdx.x * blockDim.x + threadIdx.x;
    if (t >= NB * NH * NW) return;
    int b   = t >> 16;
    int rem = t & 65535;
    int i = rem >> 8, j = rem & 255;

    const float* gb = d_g + (size_t)b * GP * GP;

    int mi[2], nj[2];
    int nm = 1, nn = 1;
    mi[0] = i + 3;
    nj[0] = j + 3;
    if (i < 3)       mi[nm++] = 2 - i;
    if (i >= NH - 3) mi[nm++] = 2 * NH + 2 - i;
    if (j < 3)       nj[nn++] = 2 - j;
    if (j >= NW - 3) nj[nn++] = 2 * NW + 2 - j;

    float r = 0.f;
    for (int a = 0; a < nm; ++a)
        for (int c = 0; c < nn; ++c)
            r += gb[mi[a] * GP + nj[c]];

    float av = a_cond[b];
    float z = input[t] - r;
    float d = z - av;
    out[t] = 0.5f * (d + sqrtf(d * d + 4.0f * av * noisy[t]));
}

// ---------------- launch ----------------
extern "C" void kernel_launch(void* const* d_in, const int* in_sizes, int n_in,
                              void* d_out, int out_size)
{
    const float* input   = (const float*)d_in[0];
    const float* noisy   = (const float*)d_in[1];
    const float* a_cond  = (const float*)d_in[2];
    const float* cw      = (const float*)d_in[3];
    const float* sf      = (const float*)d_in[4];
    const float* rw      = (const float*)d_in[5];
    const float* centers = (const float*)d_in[6];
    const float* grid    = (const float*)d_in[7];
    float* out = (float*)d_out;

    prep_weights<<<1, 64>>>(cw, sf, grid);
    prep_table<<<NF, 128>>>(rw, centers, grid);
    fused_kernel<<<dim3(4, NH, NB), 128>>>(input);
    fold_kernel<<<dim3((GP * GP + 255) / 256, NB), 256>>>();
    finish_kernel<<<(NB * NH * NW + 255) / 256, 256>>>(input, noisy, a_cond, out);
}

// round 14
// speedup vs baseline: 1.1732x; 1.1732x over previous
#include <cuda_runtime.h>
#include <stdint.h>
#include <math.h>

#define NF 64
#define NC 51
#define LG 1001
#define NB 16
#define NH 256
#define NW 256
#define GP 262
#define PSIPLANE ((size_t)NB * NH * NW)
#define PST 72

// ---------------- scratch ----------------
__device__ float  d_wn [NF * 49];
__device__ float  d_wnf[NF * 49];
__device__ float2 d_tab2[NF * 1000];
__device__ float  d_lut[3];
__device__ float  d_psi[49 * ((size_t)NB * NH * NW)]; // 205 MB
__device__ float  d_g  [NB * GP * GP];

// ---------------- helpers ----------------
__device__ __forceinline__ unsigned cvt_tf32(float v) {
    unsigned u;
    asm("cvt.rna.tf32.f32 %0, %1;" : "=r"(u) : "f"(v));
    return u;
}

__device__ __forceinline__ void mma_tf32(float& c0, float& c1, float& c2, float& c3,
                                         unsigned a0, unsigned a1, unsigned a2, unsigned a3,
                                         unsigned b0, unsigned b1) {
    asm volatile(
        "mma.sync.aligned.m16n8k8.row.col.f32.tf32.tf32.f32 "
        "{%0,%1,%2,%3}, {%4,%5,%6,%7}, {%8,%9}, {%0,%1,%2,%3};"
        : "+f"(c0), "+f"(c1), "+f"(c2), "+f"(c3)
        : "r"(a0), "r"(a1), "r"(a2), "r"(a3), "r"(b0), "r"(b1));
}

// ---------------- prep 1 ----------------
__global__ void prep_weights(const float* __restrict__ cw,
                             const float* __restrict__ sf,
                             const float* __restrict__ grid)
{
    int f = threadIdx.x;
    if (f < NF) {
        float s = 0.f;
        for (int k = 0; k < 49; ++k) s += cw[f * 49 + k];
        float mean = s / 49.0f;
        float ss = 0.f;
        for (int k = 0; k < 49; ++k) {
            float v = cw[f * 49 + k] - mean;
            ss += v * v;
        }
        float sc = sf[f] / sqrtf(ss);
        for (int k = 0; k < 49; ++k) {
            float v = (cw[f * 49 + k] - mean) * sc;
            d_wn[f * 49 + k] = v;
            int p = k / 7, q = k % 7;
            d_wnf[f * 49 + (6 - p) * 7 + (6 - q)] = v;
        }
    }
    if (threadIdx.x == 0) {
        d_lut[0] = grid[0];
        d_lut[1] = grid[LG - 1];
        d_lut[2] = 1.0f / (grid[1] - grid[0]);
    }
}

// ---------------- prep 2 ----------------
__global__ void prep_table(const float* __restrict__ rw,
                           const float* __restrict__ centers,
                           const float* __restrict__ grid)
{
    __shared__ float tl[LG];
    __shared__ float cs[NC];
    __shared__ float rs[NC];
    int f = blockIdx.x;
    int t = threadIdx.x;
    if (t < NC) { cs[t] = centers[t]; rs[t] = rw[f * NC + t]; }
    __syncthreads();
    for (int l = t; l < LG; l += blockDim.x) {
        float g = grid[l];
        float s = 0.f;
        #pragma unroll 1
        for (int c = 0; c < NC; ++c) {
            float dd = 0.25f * (g - cs[c]);
            s += rs[c] * expf(-0.5f * dd * dd);
        }
        tl[l] = s;
    }
    __syncthreads();
    for (int l = t; l < LG - 1; l += blockDim.x)
        d_tab2[f * 1000 + l] = make_float2(tl[l], tl[l + 1]);
}

// ---------------- fused kernel: one row per block, 4 x 64-px segments --------
// 128 threads (4 warps). ws/sb loaded once per block; per segment:
// patch fill -> sync -> fwd MMA + LUT -> phis(smem) -> sync -> psi MMA -> psi store.
// smem: 14336 + 14336 + 2016 + 18432 = 49120 B (fits 48KB static).
__global__ void __launch_bounds__(128) fused_kernel(const float* __restrict__ x)
{
    __shared__ unsigned ws  [56 * 64];    // fwd weights [k][f], k>=49 zero
    __shared__ unsigned sb  [64 * 56];    // adjoint weights [f][uv], uv>=49 zero
    __shared__ float    patch[7 * PST];   // 7 x 70 used, stride 72
    __shared__ unsigned phis[64 * PST];   // phi tile [f][px], raw fp32 bits

    int b  = blockIdx.y;
    int y0 = blockIdx.x;
    int tid = threadIdx.x;

    for (int t = tid; t < 56 * 64; t += 128) {
        int k = t >> 6, f = t & 63;
        ws[t] = (k < 49) ? cvt_tf32(d_wn[f * 49 + k]) : 0u;
    }
    for (int t = tid; t < 64 * 56; t += 128) {
        int f = t / 56, uv = t - f * 56;
        sb[t] = (uv < 49) ? cvt_tf32(d_wnf[f * 49 + uv]) : 0u;
    }

    float g0 = d_lut[0], gmax = d_lut[1], invstep = d_lut[2];

    int lane = tid & 31, wrp = tid >> 5;
    int lam = lane & 3;
    int grp = lane >> 2;
    int mrow = wrp * 16;

    int offA[7][2];
    #pragma unroll
    for (int kk = 0; kk < 7; ++kk) {
        #pragma unroll
        for (int h = 0; h < 2; ++h) {
            int c = kk * 8 + lam + 4 * h;
            if (c > 48) c = 48;
            offA[kk][h] = (c / 7) * PST + (c % 7);
        }
    }

    const float* xb = x + ((size_t)b << 16);

    #pragma unroll 1
    for (int seg = 0; seg < 4; ++seg) {
        int x0 = seg * 64;

        // patch fill (safe to overlap prior stage-3: disjoint buffers)
        for (int t = tid; t < 7 * 70; t += 128) {
            int r = t / 70, c = t - r * 70;
            int gi = y0 - 3 + r;
            int gj = x0 - 3 + c;
            gi = (gi < 0) ? (-1 - gi) : ((gi >= NH) ? (2 * NH - 1 - gi) : gi);
            gj = (gj < 0) ? (-1 - gj) : ((gj >= NW) ? (2 * NW - 1 - gj) : gj);
            patch[r * PST + c] = xb[(gi << 8) + gj];
        }
        __syncthreads();   // patch ready; all warps past prior stage-3 (phis free)

        // ---- stage 1: forward conv + LUT -> phis ----
        #pragma unroll 1
        for (int fc = 0; fc < 2; ++fc) {
            unsigned bfr[4][7][2];
            #pragma unroll
            for (int n = 0; n < 4; ++n)
                #pragma unroll
                for (int kk = 0; kk < 7; ++kk) {
                    bfr[n][kk][0] = ws[(kk * 8 + lam)     * 64 + fc * 32 + n * 8 + grp];
                    bfr[n][kk][1] = ws[(kk * 8 + lam + 4) * 64 + fc * 32 + n * 8 + grp];
                }

            float acc[4][4];
            #pragma unroll
            for (int n = 0; n < 4; ++n)
                #pragma unroll
                for (int j = 0; j < 4; ++j) acc[n][j] = 0.f;

            const float* pb = patch + mrow + grp;
            #pragma unroll
            for (int kk = 0; kk < 7; ++kk) {
                unsigned a0 = __float_as_uint(pb[offA[kk][0]]);
                unsigned a1 = __float_as_uint(pb[offA[kk][0] + 8]);
                unsigned a2 = __float_as_uint(pb[offA[kk][1]]);
                unsigned a3 = __float_as_uint(pb[offA[kk][1] + 8]);
                #pragma unroll
                for (int n = 0; n < 4; ++n)
                    mma_tf32(acc[n][0], acc[n][1], acc[n][2], acc[n][3],
                             a0, a1, a2, a3, bfr[n][kk][0], bfr[n][kk][1]);
            }

            #pragma unroll
            for (int n = 0; n < 4; ++n) {
                #pragma unroll
                for (int j = 0; j < 4; ++j) {
                    int f  = fc * 32 + n * 8 + 2 * lam + (j & 1);
                    int px = mrow + grp + 8 * (j >> 1);
                    float v = fminf(fmaxf(acc[n][j], g0), gmax);
                    float pos = (v - g0) * invstep;
                    int idx = (int)floorf(pos);
                    idx = idx < 0 ? 0 : (idx > 999 ? 999 : idx);
                    float fr = pos - (float)idx;
                    float2 tv = __ldg(d_tab2 + f * 1000 + idx);
                    phis[f * PST + px] = __float_as_uint(tv.x * (1.0f - fr) + tv.y * fr);
                }
            }
        }
        __syncthreads();   // phis complete; patch reads done

        // ---- stage 3: psi GEMM  psi[px][uv] = sum_f phi[px][f] * wnf[f][uv] ----
        float acc2[7][4];
        #pragma unroll
        for (int n = 0; n < 7; ++n)
            #pragma unroll
            for (int j = 0; j < 4; ++j) acc2[n][j] = 0.f;

        #pragma unroll
        for (int kk = 0; kk < 8; ++kk) {
            unsigned bf[7][2];
            #pragma unroll
            for (int n = 0; n < 7; ++n) {
                bf[n][0] = sb[(kk * 8 + lam)     * 56 + n * 8 + grp];
                bf[n][1] = sb[(kk * 8 + lam + 4) * 56 + n * 8 + grp];
            }
            unsigned a0 = phis[(kk * 8 + lam)     * PST + mrow + grp];
            unsigned a1 = phis[(kk * 8 + lam)     * PST + mrow + grp + 8];
            unsigned a2 = phis[(kk * 8 + lam + 4) * PST + mrow + grp];
            unsigned a3 = phis[(kk * 8 + lam + 4) * PST + mrow + grp + 8];
            #pragma unroll
            for (int n = 0; n < 7; ++n)
                mma_tf32(acc2[n][0], acc2[n][1], acc2[n][2], acc2[n][3],
                         a0, a1, a2, a3, bf[n][0], bf[n][1]);
        }

        size_t bpx = ((size_t)b << 16) + ((size_t)y0 << 8) + x0;
        #pragma unroll
        for (int n = 0; n < 7; ++n) {
            #pragma unroll
            for (int j = 0; j < 4; ++j) {
                int uv = n * 8 + 2 * lam + (j & 1);
                if (uv < 49) {
                    int pl = mrow + grp + 8 * (j >> 1);
                    d_psi[(size_t)uv * PSIPLANE + bpx + pl] = acc2[n][j];
                }
            }
        }
        __syncthreads();
    }
}

// ---------------- fold: g[m,n] = sum_uv psi[uv][m-6+u][n-6+v] ----------------
__global__ void __launch_bounds__(256) fold_kernel()
{
    int t = blockIdx.x * 256 + threadIdx.x;
    if (t >= GP * GP) return;
    int b = blockIdx.y;
    int m = t / GP;
    int n = t - m * GP;

    float acc = 0.f;
    #pragma unroll
    for (int u = 0; u < 7; ++u) {
        int y = m - 6 + u;
        if ((unsigned)y < (unsigned)NH) {
            const float* base = d_psi + (size_t)(u * 7) * PSIPLANE
                              + ((size_t)b << 16) + (y << 8);
            #pragma unroll
            for (int v = 0; v < 7; ++v) {
                int xx = n - 6 + v;
                if ((unsigned)xx < (unsigned)NW)
                    acc += base[(size_t)v * PSIPLANE + xx];
            }
        }
    }
    d_g[(size_t)b * GP * GP + t] = acc;
}

// ---------------- finish: fold borders + residual + prox ----------------
__global__ void finish_kernel(const float* __restrict__ input,
                              const float* __restrict__ noisy,
                              const float* __restrict__ a_cond,
                              float* __restrict__ out)
{
    int t = blockIdx.x * blockDim.x + threadIdx.x;
    if (t >= NB * NH * NW) return;
    int b   = t >> 16;
    int rem = t & 65535;
    int i = rem >> 8, j = rem & 255;

    const float* gb = d_g + (size_t)b * GP * GP;

    int mi[2], nj[2];
    int nm = 1, nn = 1;
    mi[0] = i + 3;
    nj[0] = j + 3;
    if (i < 3)       mi[nm++] = 2 - i;
    if (i >= NH - 3) mi[nm++] = 2 * NH + 2 - i;
    if (j < 3)       nj[nn++] = 2 - j;
    if (j >= NW - 3) nj[nn++] = 2 * NW + 2 - j;

    float r = 0.f;
    for (int a = 0; a < nm; ++a)
        for (int c = 0; c < nn; ++c)
            r += gb[mi[a] * GP + nj[c]];

    float av = a_cond[b];
    float z = input[t] - r;
    float d = z - av;
    out[t] = 0.5f * (d + sqrtf(d * d + 4.0f * av * noisy[t]));
}

// ---------------- launch ----------------
extern "C" void kernel_launch(void* const* d_in, const int* in_sizes, int n_in,
                              void* d_out, int out_size)
{
    const float* input   = (const float*)d_in[0];
    const float* noisy   = (const float*)d_in[1];
    const float* a_cond  = (const float*)d_in[2];
    const float* cw      = (const float*)d_in[3];
    const float* sf      = (const float*)d_in[4];
    const float* rw      = (const float*)d_in[5];
    const float* centers = (const float*)d_in[6];
    const float* grid    = (const float*)d_in[7];
    float* out = (float*)d_out;

    prep_weights<<<1, 64>>>(cw, sf, grid);
    prep_table<<<NF, 128>>>(rw, centers, grid);
    fused_kernel<<<dim3(NH, NB), 128>>>(input);
    fold_kernel<<<dim3((GP * GP + 255) / 256, NB), 256>>>();
    finish_kernel<<<(NB * NH * NW + 255) / 256, 256>>>(input, noisy, a_cond, out);
}

// round 15
// speedup vs baseline: 1.4810x; 1.2624x over previous
#include <cuda_runtime.h>
#include <cuda_fp16.h>
#include <stdint.h>
#include <math.h>

#define NF 64
#define NFC 32
#define NC 51
#define LG 1001
#define NB 16
#define NH 256
#define NW 256
#define GP 262
#define PSIPLANE ((size_t)NB * NH * NW)

// ---------------- scratch ----------------
__device__ float  d_wn [NF * 49];
__device__ float  d_wnf[NF * 49];
__device__ float2 d_tab2[NF * 1000];
__device__ float  d_lut[3];
__device__ __half d_phi[(size_t)NB * NF * NH * NW];   // 128 MB
__device__ __half d_psi[49 * ((size_t)NB * NH * NW)]; // 102 MB
__device__ float  d_g  [NB * GP * GP];

// ---------------- helpers ----------------
__device__ __forceinline__ void cp_async16(void* sdst, const void* gsrc) {
    unsigned int sa = (unsigned int)__cvta_generic_to_shared(sdst);
    asm volatile("cp.async.cg.shared.global [%0], [%1], 16;\n" :: "r"(sa), "l"(gsrc));
}
__device__ __forceinline__ void cp_commit() { asm volatile("cp.async.commit_group;\n"); }
__device__ __forceinline__ void cp_wait0()  { asm volatile("cp.async.wait_group 0;\n"); }
__device__ __forceinline__ void cp_wait1()  { asm volatile("cp.async.wait_group 1;\n"); }

__device__ __forceinline__ unsigned cvt_tf32(float v) {
    unsigned u;
    asm("cvt.rna.tf32.f32 %0, %1;" : "=r"(u) : "f"(v));
    return u;
}

__device__ __forceinline__ void mma_tf32(float& c0, float& c1, float& c2, float& c3,
                                         unsigned a0, unsigned a1, unsigned a2, unsigned a3,
                                         unsigned b0, unsigned b1) {
    asm volatile(
        "mma.sync.aligned.m16n8k8.row.col.f32.tf32.tf32.f32 "
        "{%0,%1,%2,%3}, {%4,%5,%6,%7}, {%8,%9}, {%0,%1,%2,%3};"
        : "+f"(c0), "+f"(c1), "+f"(c2), "+f"(c3)
        : "r"(a0), "r"(a1), "r"(a2), "r"(a3), "r"(b0), "r"(b1));
}

// ---------------- prep 1 ----------------
__global__ void prep_weights(const float* __restrict__ cw,
                             const float* __restrict__ sf,
                             const float* __restrict__ grid)
{
    int f = threadIdx.x;
    if (f < NF) {
        float s = 0.f;
        for (int k = 0; k < 49; ++k) s += cw[f * 49 + k];
        float mean = s / 49.0f;
        float ss = 0.f;
        for (int k = 0; k < 49; ++k) {
            float v = cw[f * 49 + k] - mean;
            ss += v * v;
        }
        float sc = sf[f] / sqrtf(ss);
        for (int k = 0; k < 49; ++k) {
            float v = (cw[f * 49 + k] - mean) * sc;
            d_wn[f * 49 + k] = v;
            int p = k / 7, q = k % 7;
            d_wnf[f * 49 + (6 - p) * 7 + (6 - q)] = v;
        }
    }
    if (threadIdx.x == 0) {
        d_lut[0] = grid[0];
        d_lut[1] = grid[LG - 1];
        d_lut[2] = 1.0f / (grid[1] - grid[0]);
    }
}

// ---------------- prep 2 ----------------
__global__ void prep_table(const float* __restrict__ rw,
                           const float* __restrict__ centers,
                           const float* __restrict__ grid)
{
    __shared__ float tl[LG];
    __shared__ float cs[NC];
    __shared__ float rs[NC];
    int f = blockIdx.x;
    int t = threadIdx.x;
    if (t < NC) { cs[t] = centers[t]; rs[t] = rw[f * NC + t]; }
    __syncthreads();
    for (int l = t; l < LG; l += blockDim.x) {
        float g = grid[l];
        float s = 0.f;
        #pragma unroll 1
        for (int c = 0; c < NC; ++c) {
            float dd = 0.25f * (g - cs[c]);
            s += rs[c] * expf(-0.5f * dd * dd);
        }
        tl[l] = s;
    }
    __syncthreads();
    for (int l = t; l < LG - 1; l += blockDim.x)
        d_tab2[f * 1000 + l] = make_float2(tl[l], tl[l + 1]);
}

// ---------------- kernel B: forward conv via mma.sync tf32 + LUT -> phi(fp16) ----
__global__ void __launch_bounds__(128) fwd_kernel(const float* __restrict__ x)
{
    __shared__ float    xs[14][72];
    __shared__ unsigned ws[56 * 32];

    int b  = blockIdx.z;
    int i0 = blockIdx.y * 8;
    int xt = blockIdx.x & 3;
    int fc = blockIdx.x >> 2;
    int x0 = xt * 64;
    int f0 = fc * NFC;
    int tid = threadIdx.x;

    const float* xb_ptr = x + (size_t)b * NH * NW;

    for (int tpos = tid; tpos < 14 * 70; tpos += 128) {
        int r = tpos / 70, c = tpos - r * 70;
        int gi = i0 - 3 + r;
        int gj = x0 - 3 + c;
        gi = (gi < 0) ? (-1 - gi) : ((gi >= NH) ? (2 * NH - 1 - gi) : gi);
        gj = (gj < 0) ? (-1 - gj) : ((gj >= NW) ? (2 * NW - 1 - gj) : gj);
        xs[r][c] = xb_ptr[gi * NW + gj];
    }
    for (int tpos = tid; tpos < 56 * 32; tpos += 128) {
        int k = tpos >> 5, n = tpos & 31;
        ws[tpos] = (k < 49) ? cvt_tf32(d_wn[(f0 + n) * 49 + k]) : 0u;
    }
    __syncthreads();

    float g0 = d_lut[0], gmax = d_lut[1], invstep = d_lut[2];

    int lane = tid & 31, wrp = tid >> 5;
    int lam = lane & 3;
    int grp = lane >> 2;

    int offA[7][2];
    #pragma unroll
    for (int kk = 0; kk < 7; ++kk) {
        #pragma unroll
        for (int h = 0; h < 2; ++h) {
            int c = kk * 8 + lam + 4 * h;
            if (c > 48) c = 48;
            offA[kk][h] = (c / 7) * 72 + (c % 7);
        }
    }

    unsigned bfr[4][7][2];
    #pragma unroll
    for (int n = 0; n < 4; ++n)
        #pragma unroll
        for (int kk = 0; kk < 7; ++kk) {
            bfr[n][kk][0] = ws[(kk * 8 + lam) * 32 + n * 8 + grp];
            bfr[n][kk][1] = ws[(kk * 8 + lam + 4) * 32 + n * 8 + grp];
        }

    const float* xsf = &xs[0][0];

    #pragma unroll 1
    for (int mt = 0; mt < 8; ++mt) {
        int py = wrp * 2 + (mt >> 2);
        int xb = (mt & 3) * 16;
        int base = py * 72 + xb + grp;

        float acc[4][4];
        #pragma unroll
        for (int n = 0; n < 4; ++n)
            #pragma unroll
            for (int j = 0; j < 4; ++j) acc[n][j] = 0.f;

        #pragma unroll
        for (int kk = 0; kk < 7; ++kk) {
            unsigned a0 = __float_as_uint(xsf[base +     offA[kk][0]]);
            unsigned a1 = __float_as_uint(xsf[base + 8 + offA[kk][0]]);
            unsigned a2 = __float_as_uint(xsf[base +     offA[kk][1]]);
            unsigned a3 = __float_as_uint(xsf[base + 8 + offA[kk][1]]);
            #pragma unroll
            for (int n = 0; n < 4; ++n)
                mma_tf32(acc[n][0], acc[n][1], acc[n][2], acc[n][3],
                         a0, a1, a2, a3, bfr[n][kk][0], bfr[n][kk][1]);
        }

        int y = i0 + py;
        #pragma unroll
        for (int n = 0; n < 4; ++n) {
            #pragma unroll
            for (int j = 0; j < 4; ++j) {
                int f  = f0 + n * 8 + 2 * lam + (j & 1);
                int px = x0 + xb + grp + ((j >> 1) << 3);
                float v = fminf(fmaxf(acc[n][j], g0), gmax);
                float pos = (v - g0) * invstep;          // >= 0
                int idx = min(__float2int_rd(pos), 999);
                float fr = pos - (float)idx;
                float2 tv = __ldg(d_tab2 + f * 1000 + idx);
                float ph = fmaf(fr, tv.y - tv.x, tv.x);
                d_phi[(((size_t)(b * NF + f)) << 16) + (y << 8) + px] = __float2half(ph);
            }
        }
    }
}

// ---------------- kernel C1: psi GEMM (fp16 phi in, fp16 psi out), pipelined ----
#define KC 32
#define SA_H 136             /* halves per filter row */
#define SB_STRIDE 57
#define NSTEP 8              /* 4 tiles x 2 k-chunks */
__global__ void __launch_bounds__(128) psi_kernel()
{
    __shared__ __half   sa[2][KC * SA_H];        // 2 x 8.5 KB
    __shared__ unsigned sb[64 * SB_STRIDE];      // 14.25 KB

    int b     = blockIdx.y;
    int tile0 = blockIdx.x * 4;
    int tid   = threadIdx.x;

    for (int c = tid; c < 64 * 56; c += 128) {
        int f = c / 56, uv = c - f * 56;
        sb[f * SB_STRIDE + uv] = (uv < 49) ? cvt_tf32(d_wnf[f * 49 + uv]) : 0u;
    }

    const __half* phib = d_phi + (((size_t)b * NF) << 16);

    // stage step s (tile = s/2, kchunk = s%2) into buffer s&1; 16B = 8 halves
    #define PSI_STAGE(S)                                                        \
        {                                                                       \
            int t_ = (S) >> 1, kc_ = (S) & 1;                                   \
            const __half* src = phib + (((size_t)(kc_ * KC)) << 16)             \
                              + (size_t)(tile0 + t_) * 128;                     \
            for (int c = tid; c < KC * 16; c += 128) {                          \
                int f_ = c >> 4, c8 = c & 15;                                   \
                cp_async16(&sa[(S) & 1][f_ * SA_H + c8 * 8],                    \
                           src + (((size_t)f_) << 16) + c8 * 8);                \
            }                                                                   \
            cp_commit();                                                        \
        }

    PSI_STAGE(0)

    int lane = tid & 31, wrp = tid >> 5;
    int lam = lane & 3;
    int grp = lane >> 2;

    float acc[2][7][4];

    #pragma unroll 1
    for (int s = 0; s < NSTEP; ++s) {
        int kc = s & 1;

        if (s + 1 < NSTEP) { PSI_STAGE(s + 1) cp_wait1(); }
        else               { cp_wait0(); }
        __syncthreads();

        if (kc == 0) {
            #pragma unroll
            for (int mt = 0; mt < 2; ++mt)
                #pragma unroll
                for (int n = 0; n < 7; ++n)
                    #pragma unroll
                    for (int j = 0; j < 4; ++j) acc[mt][n][j] = 0.f;
        }

        const __half* sab = sa[s & 1];
        #pragma unroll
        for (int kk = 0; kk < 4; ++kk) {
            int fg = kc * KC + kk * 8;
            unsigned bf[7][2];
            #pragma unroll
            for (int n = 0; n < 7; ++n) {
                bf[n][0] = sb[(fg + lam)     * SB_STRIDE + n * 8 + grp];
                bf[n][1] = sb[(fg + lam + 4) * SB_STRIDE + n * 8 + grp];
            }
            #pragma unroll
            for (int mt = 0; mt < 2; ++mt) {
                int mrow = (wrp * 2 + mt) * 16;
                unsigned a0 = __float_as_uint(__half2float(sab[(kk * 8 + lam)     * SA_H + mrow + grp]));
                unsigned a1 = __float_as_uint(__half2float(sab[(kk * 8 + lam)     * SA_H + mrow + grp + 8]));
                unsigned a2 = __float_as_uint(__half2float(sab[(kk * 8 + lam + 4) * SA_H + mrow + grp]));
                unsigned a3 = __float_as_uint(__half2float(sab[(kk * 8 + lam + 4) * SA_H + mrow + grp + 8]));
                #pragma unroll
                for (int n = 0; n < 7; ++n)
                    mma_tf32(acc[mt][n][0], acc[mt][n][1], acc[mt][n][2], acc[mt][n][3],
                             a0, a1, a2, a3, bf[n][0], bf[n][1]);
            }
        }

        if (kc == 1) {
            size_t bpx = ((size_t)b << 16) + (size_t)(tile0 + (s >> 1)) * 128;
            #pragma unroll
            for (int mt = 0; mt < 2; ++mt) {
                #pragma unroll
                for (int n = 0; n < 7; ++n) {
                    #pragma unroll
                    for (int j = 0; j < 4; ++j) {
                        int uv = n * 8 + 2 * lam + (j & 1);
                        if (uv < 49) {
                            int pl = (wrp * 2 + mt) * 16 + grp + 8 * (j >> 1);
                            d_psi[(size_t)uv * PSIPLANE + bpx + pl] =
                                __float2half(acc[mt][n][j]);
                        }
                    }
                }
            }
        }
        __syncthreads();
    }
    #undef PSI_STAGE
}

// ---------------- kernel C2: fold (fp16 psi in, fp32 g out) ----------------
__global__ void __launch_bounds__(256) fold_kernel()
{
    int t = blockIdx.x * 256 + threadIdx.x;
    if (t >= GP * GP) return;
    int b = blockIdx.y;
    int m = t / GP;
    int n = t - m * GP;

    float acc = 0.f;
    #pragma unroll
    for (int u = 0; u < 7; ++u) {
        int y = m - 6 + u;
        if ((unsigned)y < (unsigned)NH) {
            const __half* base = d_psi + (size_t)(u * 7) * PSIPLANE
                               + ((size_t)b << 16) + (y << 8);
            #pragma unroll
            for (int v = 0; v < 7; ++v) {
                int xx = n - 6 + v;
                if ((unsigned)xx < (unsigned)NW)
                    acc += __half2float(base[(size_t)v * PSIPLANE + xx]);
            }
        }
    }
    d_g[(size_t)b * GP * GP + t] = acc;
}

// ---------------- kernel D: fold borders + residual + prox ----------------
__global__ void finish_kernel(const float* __restrict__ input,
                              const float* __restrict__ noisy,
                              const float* __restrict__ a_cond,
                              float* __restrict__ out)
{
    int t = blockIdx.x * blockDim.x + threadIdx.x;
    if (t >= NB * NH * NW) return;
    int b   = t >> 16;
    int rem = t & 65535;
    int i = rem >> 8, j = rem & 255;

    const float* gb = d_g + (size_t)b * GP * GP;

    int mi[2], nj[2];
    int nm = 1, nn = 1;
    mi[0] = i + 3;
    nj[0] = j + 3;
    if (i < 3)       mi[nm++] = 2 - i;
    if (i >= NH - 3) mi[nm++] = 2 * NH + 2 - i;
    if (j < 3)       nj[nn++] = 2 - j;
    if (j >= NW - 3) nj[nn++] = 2 * NW + 2 - j;

    float r = 0.f;
    for (int a = 0; a < nm; ++a)
        for (int c = 0; c < nn; ++c)
            r += gb[mi[a] * GP + nj[c]];

    float av = a_cond[b];
    float z = input[t] - r;
    float d = z - av;
    out[t] = 0.5f * (d + sqrtf(d * d + 4.0f * av * noisy[t]));
}

// ---------------- launch ----------------
extern "C" void kernel_launch(void* const* d_in, const int* in_sizes, int n_in,
                              void* d_out, int out_size)
{
    const float* input   = (const float*)d_in[0];
    const float* noisy   = (const float*)d_in[1];
    const float* a_cond  = (const float*)d_in[2];
    const float* cw      = (const float*)d_in[3];
    const float* sf      = (const float*)d_in[4];
    const float* rw      = (const float*)d_in[5];
    const float* centers = (const float*)d_in[6];
    const float* grid    = (const float*)d_in[7];
    float* out = (float*)d_out;

    prep_weights<<<1, 64>>>(cw, sf, grid);
    prep_table<<<NF, 128>>>(rw, centers, grid);
    fwd_kernel<<<dim3(8, 32, NB), 128>>>(input);
    psi_kernel<<<dim3(128, NB), 128>>>();
    fold_kernel<<<dim3((GP * GP + 255) / 256, NB), 256>>>();
    finish_kernel<<<(NB * NH * NW + 255) / 256, 256>>>(input, noisy, a_cond, out);
}

// round 16
// speedup vs baseline: 1.5572x; 1.0514x over previous
#include <cuda_runtime.h>
#include <cuda_fp16.h>
#include <stdint.h>
#include <math.h>

#define NF 64
#define NFC 32
#define NC 51
#define LG 1001
#define NB 16
#define NH 256
#define NW 256
#define GP 262
#define PSIPLANE ((size_t)NB * NH * NW)

// ---------------- scratch ----------------
__device__ float  d_wn [NF * 49];
__device__ float  d_wnf[NF * 49];
__device__ float2 d_tab2[NF * 1000];
__device__ float  d_lut[3];
// phi layout: [b][px][f]  (f contiguous, 64 halves = 128B per px)
__device__ __align__(16) __half d_phi[(size_t)NB * NH * NW * NF];   // 128 MB
__device__ __align__(16) __half d_psi[49 * ((size_t)NB * NH * NW)]; // 102 MB
__device__ float  d_g  [NB * GP * GP];

// ---------------- helpers ----------------
__device__ __forceinline__ void cp_async16(void* sdst, const void* gsrc) {
    unsigned int sa = (unsigned int)__cvta_generic_to_shared(sdst);
    asm volatile("cp.async.cg.shared.global [%0], [%1], 16;\n" :: "r"(sa), "l"(gsrc));
}
__device__ __forceinline__ void cp_commit() { asm volatile("cp.async.commit_group;\n"); }
__device__ __forceinline__ void cp_wait0()  { asm volatile("cp.async.wait_group 0;\n"); }
__device__ __forceinline__ void cp_wait1()  { asm volatile("cp.async.wait_group 1;\n"); }

__device__ __forceinline__ unsigned cvt_tf32(float v) {
    unsigned u;
    asm("cvt.rna.tf32.f32 %0, %1;" : "=r"(u) : "f"(v));
    return u;
}

__device__ __forceinline__ void mma_tf32(float& c0, float& c1, float& c2, float& c3,
                                         unsigned a0, unsigned a1, unsigned a2, unsigned a3,
                                         unsigned b0, unsigned b1) {
    asm volatile(
        "mma.sync.aligned.m16n8k8.row.col.f32.tf32.tf32.f32 "
        "{%0,%1,%2,%3}, {%4,%5,%6,%7}, {%8,%9}, {%0,%1,%2,%3};"
        : "+f"(c0), "+f"(c1), "+f"(c2), "+f"(c3)
        : "r"(a0), "r"(a1), "r"(a2), "r"(a3), "r"(b0), "r"(b1));
}

__device__ __forceinline__ void mma_f16(float& c0, float& c1, float& c2, float& c3,
                                        unsigned a0, unsigned a1, unsigned a2, unsigned a3,
                                        unsigned b0, unsigned b1) {
    asm volatile(
        "mma.sync.aligned.m16n8k16.row.col.f32.f16.f16.f32 "
        "{%0,%1,%2,%3}, {%4,%5,%6,%7}, {%8,%9}, {%0,%1,%2,%3};"
        : "+f"(c0), "+f"(c1), "+f"(c2), "+f"(c3)
        : "r"(a0), "r"(a1), "r"(a2), "r"(a3), "r"(b0), "r"(b1));
}

// ---------------- prep 1 ----------------
__global__ void prep_weights(const float* __restrict__ cw,
                             const float* __restrict__ sf,
                             const float* __restrict__ grid)
{
    int f = threadIdx.x;
    if (f < NF) {
        float s = 0.f;
        for (int k = 0; k < 49; ++k) s += cw[f * 49 + k];
        float mean = s / 49.0f;
        float ss = 0.f;
        for (int k = 0; k < 49; ++k) {
            float v = cw[f * 49 + k] - mean;
            ss += v * v;
        }
        float sc = sf[f] / sqrtf(ss);
        for (int k = 0; k < 49; ++k) {
            float v = (cw[f * 49 + k] - mean) * sc;
            d_wn[f * 49 + k] = v;
            int p = k / 7, q = k % 7;
            d_wnf[f * 49 + (6 - p) * 7 + (6 - q)] = v;
        }
    }
    if (threadIdx.x == 0) {
        d_lut[0] = grid[0];
        d_lut[1] = grid[LG - 1];
        d_lut[2] = 1.0f / (grid[1] - grid[0]);
    }
}

// ---------------- prep 2 ----------------
__global__ void prep_table(const float* __restrict__ rw,
                           const float* __restrict__ centers,
                           const float* __restrict__ grid)
{
    __shared__ float tl[LG];
    __shared__ float cs[NC];
    __shared__ float rs[NC];
    int f = blockIdx.x;
    int t = threadIdx.x;
    if (t < NC) { cs[t] = centers[t]; rs[t] = rw[f * NC + t]; }
    __syncthreads();
    for (int l = t; l < LG; l += blockDim.x) {
        float g = grid[l];
        float s = 0.f;
        #pragma unroll 1
        for (int c = 0; c < NC; ++c) {
            float dd = 0.25f * (g - cs[c]);
            s += rs[c] * expf(-0.5f * dd * dd);
        }
        tl[l] = s;
    }
    __syncthreads();
    for (int l = t; l < LG - 1; l += blockDim.x)
        d_tab2[f * 1000 + l] = make_float2(tl[l], tl[l + 1]);
}

// ---------------- kernel B: forward conv (tf32 mma) + LUT -> phi[px][f] fp16 ----
__global__ void __launch_bounds__(128) fwd_kernel(const float* __restrict__ x)
{
    __shared__ float    xs[14][72];
    __shared__ unsigned ws[56 * 32];

    int b  = blockIdx.z;
    int i0 = blockIdx.y * 8;
    int xt = blockIdx.x & 3;
    int fc = blockIdx.x >> 2;
    int x0 = xt * 64;
    int f0 = fc * NFC;
    int tid = threadIdx.x;

    const float* xb_ptr = x + (size_t)b * NH * NW;

    for (int tpos = tid; tpos < 14 * 70; tpos += 128) {
        int r = tpos / 70, c = tpos - r * 70;
        int gi = i0 - 3 + r;
        int gj = x0 - 3 + c;
        gi = (gi < 0) ? (-1 - gi) : ((gi >= NH) ? (2 * NH - 1 - gi) : gi);
        gj = (gj < 0) ? (-1 - gj) : ((gj >= NW) ? (2 * NW - 1 - gj) : gj);
        xs[r][c] = xb_ptr[gi * NW + gj];
    }
    for (int tpos = tid; tpos < 56 * 32; tpos += 128) {
        int k = tpos >> 5, n = tpos & 31;
        ws[tpos] = (k < 49) ? cvt_tf32(d_wn[(f0 + n) * 49 + k]) : 0u;
    }
    __syncthreads();

    float g0 = d_lut[0], invstep = d_lut[2];

    int lane = tid & 31, wrp = tid >> 5;
    int lam = lane & 3;
    int grp = lane >> 2;

    int offA[7][2];
    #pragma unroll
    for (int kk = 0; kk < 7; ++kk) {
        #pragma unroll
        for (int h = 0; h < 2; ++h) {
            int c = kk * 8 + lam + 4 * h;
            if (c > 48) c = 48;
            offA[kk][h] = (c / 7) * 72 + (c % 7);
        }
    }

    unsigned bfr[4][7][2];
    #pragma unroll
    for (int n = 0; n < 4; ++n)
        #pragma unroll
        for (int kk = 0; kk < 7; ++kk) {
            bfr[n][kk][0] = ws[(kk * 8 + lam) * 32 + n * 8 + grp];
            bfr[n][kk][1] = ws[(kk * 8 + lam + 4) * 32 + n * 8 + grp];
        }

    const float* xsf = &xs[0][0];

    #pragma unroll 1
    for (int mt = 0; mt < 8; ++mt) {
        int py = wrp * 2 + (mt >> 2);
        int xb = (mt & 3) * 16;
        int base = py * 72 + xb + grp;

        float acc[4][4];
        #pragma unroll
        for (int n = 0; n < 4; ++n)
            #pragma unroll
            for (int j = 0; j < 4; ++j) acc[n][j] = 0.f;

        #pragma unroll
        for (int kk = 0; kk < 7; ++kk) {
            unsigned a0 = __float_as_uint(xsf[base +     offA[kk][0]]);
            unsigned a1 = __float_as_uint(xsf[base + 8 + offA[kk][0]]);
            unsigned a2 = __float_as_uint(xsf[base +     offA[kk][1]]);
            unsigned a3 = __float_as_uint(xsf[base + 8 + offA[kk][1]]);
            #pragma unroll
            for (int n = 0; n < 4; ++n)
                mma_tf32(acc[n][0], acc[n][1], acc[n][2], acc[n][3],
                         a0, a1, a2, a3, bfr[n][kk][0], bfr[n][kk][1]);
        }

        // epilogue: LUT (clamps provably dead: |u| <= 0.7 << 100) + half2 stores
        int y = i0 + py;
        #pragma unroll
        for (int n = 0; n < 4; ++n) {
            int fbase = f0 + n * 8 + 2 * lam;
            const float2* tf0 = d_tab2 + (fbase)     * 1000;
            const float2* tf1 = d_tab2 + (fbase + 1) * 1000;
            #pragma unroll
            for (int h = 0; h < 2; ++h) {
                float v0 = acc[n][h * 2];        // f = fbase,   px
                float v1 = acc[n][h * 2 + 1];    // f = fbase+1, px
                float pos0 = (v0 - g0) * invstep;
                float pos1 = (v1 - g0) * invstep;
                int idx0 = __float2int_rd(pos0);
                int idx1 = __float2int_rd(pos1);
                float fr0 = pos0 - (float)idx0;
                float fr1 = pos1 - (float)idx1;
                float2 tv0 = __ldg(tf0 + idx0);
                float2 tv1 = __ldg(tf1 + idx1);
                float p0 = fmaf(fr0, tv0.y - tv0.x, tv0.x);
                float p1 = fmaf(fr1, tv1.y - tv1.x, tv1.x);
                int px = x0 + xb + grp + h * 8;
                size_t addr = (((size_t)(b) << 16) + (y << 8) + px) * NF + fbase;
                *reinterpret_cast<__half2*>(&d_phi[addr]) = __floats2half2_rn(p0, p1);
            }
        }
    }
}

// ---------------- kernel C1: psi GEMM, fp16 mma, pipelined ----------------
// psi[px][uv] = sum_f phi[px][f] * wnf[f][uv];  A=[128px][64f] fp16, B=[uv][f] fp16.
#define SA_S 72              /* halves per px row (padded from 64) */
#define SB_S 72              /* halves per uv row */
__global__ void __launch_bounds__(128) psi_kernel()
{
    __shared__ __half sa[2][128 * SA_S];   // 2 x 18 KB
    __shared__ __half sb[56 * SB_S];       // 7.9 KB

    int b     = blockIdx.y;
    int tile0 = blockIdx.x * 4;
    int tid   = threadIdx.x;

    // B: wnf as fp16, [uv][f]
    for (int c = tid; c < 56 * 64; c += 128) {
        int uv = c >> 6, f = c & 63;
        sb[uv * SB_S + f] = (uv < 49) ? __float2half(d_wnf[f * 49 + uv]) : __half(0.f);
    }

    // stage tile T into buffer BUF: 128 px rows x 128B
    #define PSI_STAGE(T, BUF)                                                   \
        {                                                                       \
            size_t srcb = (((size_t)b << 16) + (size_t)(T) * 128) * NF;         \
            for (int c = tid; c < 128 * 8; c += 128) {                          \
                int px = c >> 3, c8 = c & 7;                                    \
                cp_async16(&sa[BUF][px * SA_S + c8 * 8],                        \
                           d_phi + srcb + (size_t)px * NF + c8 * 8);            \
            }                                                                   \
            cp_commit();                                                        \
        }

    PSI_STAGE(tile0, 0)

    int lane = tid & 31, wrp = tid >> 5;
    int lam = lane & 3;
    int grp = lane >> 2;

    #pragma unroll 1
    for (int s = 0; s < 4; ++s) {
        if (s + 1 < 4) { PSI_STAGE(tile0 + s + 1, (s + 1) & 1) cp_wait1(); }
        else           { cp_wait0(); }
        __syncthreads();

        float acc[2][7][4];
        #pragma unroll
        for (int mt = 0; mt < 2; ++mt)
            #pragma unroll
            for (int n = 0; n < 7; ++n)
                #pragma unroll
                for (int j = 0; j < 4; ++j) acc[mt][n][j] = 0.f;

        const __half* sab = sa[s & 1];
        #pragma unroll
        for (int kk = 0; kk < 4; ++kk) {
            int kb = kk * 16 + 2 * lam;
            unsigned bf[7][2];
            #pragma unroll
            for (int n = 0; n < 7; ++n) {
                const __half* r = sb + (n * 8 + grp) * SB_S + kb;
                bf[n][0] = *reinterpret_cast<const unsigned*>(r);
                bf[n][1] = *reinterpret_cast<const unsigned*>(r + 8);
            }
            #pragma unroll
            for (int mt = 0; mt < 2; ++mt) {
                int mrow = (wrp * 2 + mt) * 16 + grp;
                const __half* ra = sab + mrow * SA_S + kb;
                unsigned a0 = *reinterpret_cast<const unsigned*>(ra);
                unsigned a1 = *reinterpret_cast<const unsigned*>(ra + 8 * SA_S);
                unsigned a2 = *reinterpret_cast<const unsigned*>(ra + 8);
                unsigned a3 = *reinterpret_cast<const unsigned*>(ra + 8 * SA_S + 8);
                #pragma unroll
                for (int n = 0; n < 7; ++n)
                    mma_f16(acc[mt][n][0], acc[mt][n][1], acc[mt][n][2], acc[mt][n][3],
                            a0, a1, a2, a3, bf[n][0], bf[n][1]);
            }
        }

        size_t bpx = ((size_t)b << 16) + (size_t)(tile0 + s) * 128;
        #pragma unroll
        for (int mt = 0; mt < 2; ++mt) {
            #pragma unroll
            for (int n = 0; n < 7; ++n) {
                #pragma unroll
                for (int j = 0; j < 4; ++j) {
                    int uv = n * 8 + 2 * lam + (j & 1);
                    if (uv < 49) {
                        int pl = (wrp * 2 + mt) * 16 + grp + 8 * (j >> 1);
                        d_psi[(size_t)uv * PSIPLANE + bpx + pl] =
                            __float2half(acc[mt][n][j]);
                    }
                }
            }
        }
        __syncthreads();
    }
    #undef PSI_STAGE
}

// ---------------- kernel C2: fold (fp16 psi in, fp32 g out) ----------------
__global__ void __launch_bounds__(256) fold_kernel()
{
    int t = blockIdx.x * 256 + threadIdx.x;
    if (t >= GP * GP) return;
    int b = blockIdx.y;
    int m = t / GP;
    int n = t - m * GP;

    float acc = 0.f;
    #pragma unroll
    for (int u = 0; u < 7; ++u) {
        int y = m - 6 + u;
        if ((unsigned)y < (unsigned)NH) {
            const __half* base = d_psi + (size_t)(u * 7) * PSIPLANE
                               + ((size_t)b << 16) + (y << 8);
            #pragma unroll
            for (int v = 0; v < 7; ++v) {
                int xx = n - 6 + v;
                if ((unsigned)xx < (unsigned)NW)
                    acc += __half2float(base[(size_t)v * PSIPLANE + xx]);
            }
        }
    }
    d_g[(size_t)b * GP * GP + t] = acc;
}

// ---------------- kernel D: fold borders + residual + prox ----------------
__global__ void finish_kernel(const float* __restrict__ input,
                              const float* __restrict__ noisy,
                              const float* __restrict__ a_cond,
                              float* __restrict__ out)
{
    int t = blockIdx.x * blockDim.x + threadIdx.x;
    if (t >= NB * NH * NW) return;
    int b   = t >> 16;
    int rem = t & 65535;
    int i = rem >> 8, j = rem & 255;

    const float* gb = d_g + (size_t)b * GP * GP;

    int mi[2], nj[2];
    int nm = 1, nn = 1;
    mi[0] = i + 3;
    nj[0] = j + 3;
    if (i < 3)       mi[nm++] = 2 - i;
    if (i >= NH - 3) mi[nm++] = 2 * NH + 2 - i;
    if (j < 3)       nj[nn++] = 2 - j;
    if (j >= NW - 3) nj[nn++] = 2 * NW + 2 - j;

    float r = 0.f;
    for (int a = 0; a < nm; ++a)
        for (int c = 0; c < nn; ++c)
            r += gb[mi[a] * GP + nj[c]];

    float av = a_cond[b];
    float z = input[t] - r;
    float d = z - av;
    out[t] = 0.5f * (d + sqrtf(d * d + 4.0f * av * noisy[t]));
}

// ---------------- launch ----------------
extern "C" void kernel_launch(void* const* d_in, const int* in_sizes, int n_in,
                              void* d_out, int out_size)
{
    const float* input   = (const float*)d_in[0];
    const float* noisy   = (const float*)d_in[1];
    const float* a_cond  = (const float*)d_in[2];
    const float* cw      = (const float*)d_in[3];
    const float* sf      = (const float*)d_in[4];
    const float* rw      = (const float*)d_in[5];
    const float* centers = (const float*)d_in[6];
    const float* grid    = (const float*)d_in[7];
    float* out = (float*)d_out;

    prep_weights<<<1, 64>>>(cw, sf, grid);
    prep_table<<<NF, 128>>>(rw, centers, grid);
    fwd_kernel<<<dim3(8, 32, NB), 128>>>(input);
    psi_kernel<<<dim3(128, NB), 128>>>();
    fold_kernel<<<dim3((GP * GP + 255) / 256, NB), 256>>>();
    finish_kernel<<<(NB * NH * NW + 255) / 256, 256>>>(input, noisy, a_cond, out);
}

// round 17
// speedup vs baseline: 1.6221x; 1.0417x over previous
#include <cuda_runtime.h>
#include <cuda_fp16.h>
#include <stdint.h>
#include <math.h>

#define NF 64
#define NFC 32
#define NC 51
#define LG 1001
#define NB 16
#define NH 256
#define NW 256
#define GP 262
#define PSIPLANE ((size_t)NB * NH * NW)

// ---------------- scratch ----------------
__device__ float  d_wn [NF * 49];
__device__ float  d_wnf[NF * 49];
__device__ float2 d_tab2[NF * 1000];
__device__ float  d_lut[3];
// phi layout: [b][px][f]  (f contiguous, 64 halves = 128B per px)
__device__ __align__(16) __half d_phi[(size_t)NB * NH * NW * NF];   // 128 MB
__device__ __align__(16) __half d_psi[49 * ((size_t)NB * NH * NW)]; // 102 MB
__device__ float  d_g  [NB * GP * GP];

// ---------------- helpers ----------------
__device__ __forceinline__ void cp_async16(void* sdst, const void* gsrc) {
    unsigned int sa = (unsigned int)__cvta_generic_to_shared(sdst);
    asm volatile("cp.async.cg.shared.global [%0], [%1], 16;\n" :: "r"(sa), "l"(gsrc));
}
__device__ __forceinline__ void cp_commit() { asm volatile("cp.async.commit_group;\n"); }
__device__ __forceinline__ void cp_wait0()  { asm volatile("cp.async.wait_group 0;\n"); }
__device__ __forceinline__ void cp_wait1()  { asm volatile("cp.async.wait_group 1;\n"); }

__device__ __forceinline__ void mma_f16(float& c0, float& c1, float& c2, float& c3,
                                        unsigned a0, unsigned a1, unsigned a2, unsigned a3,
                                        unsigned b0, unsigned b1) {
    asm volatile(
        "mma.sync.aligned.m16n8k16.row.col.f32.f16.f16.f32 "
        "{%0,%1,%2,%3}, {%4,%5,%6,%7}, {%8,%9}, {%0,%1,%2,%3};"
        : "+f"(c0), "+f"(c1), "+f"(c2), "+f"(c3)
        : "r"(a0), "r"(a1), "r"(a2), "r"(a3), "r"(b0), "r"(b1));
}

// ---------------- prep 1 ----------------
__global__ void prep_weights(const float* __restrict__ cw,
                             const float* __restrict__ sf,
                             const float* __restrict__ grid)
{
    int f = threadIdx.x;
    if (f < NF) {
        float s = 0.f;
        for (int k = 0; k < 49; ++k) s += cw[f * 49 + k];
        float mean = s / 49.0f;
        float ss = 0.f;
        for (int k = 0; k < 49; ++k) {
            float v = cw[f * 49 + k] - mean;
            ss += v * v;
        }
        float sc = sf[f] / sqrtf(ss);
        for (int k = 0; k < 49; ++k) {
            float v = (cw[f * 49 + k] - mean) * sc;
            d_wn[f * 49 + k] = v;
            int p = k / 7, q = k % 7;
            d_wnf[f * 49 + (6 - p) * 7 + (6 - q)] = v;
        }
    }
    if (threadIdx.x == 0) {
        d_lut[0] = grid[0];
        d_lut[1] = grid[LG - 1];
        d_lut[2] = 1.0f / (grid[1] - grid[0]);
    }
}

// ---------------- prep 2 ----------------
__global__ void prep_table(const float* __restrict__ rw,
                           const float* __restrict__ centers,
                           const float* __restrict__ grid)
{
    __shared__ float tl[LG];
    __shared__ float cs[NC];
    __shared__ float rs[NC];
    int f = blockIdx.x;
    int t = threadIdx.x;
    if (t < NC) { cs[t] = centers[t]; rs[t] = rw[f * NC + t]; }
    __syncthreads();
    for (int l = t; l < LG; l += blockDim.x) {
        float g = grid[l];
        float s = 0.f;
        #pragma unroll 1
        for (int c = 0; c < NC; ++c) {
            float dd = 0.25f * (g - cs[c]);
            s += rs[c] * expf(-0.5f * dd * dd);
        }
        tl[l] = s;
    }
    __syncthreads();
    for (int l = t; l < LG - 1; l += blockDim.x)
        d_tab2[f * 1000 + l] = make_float2(tl[l], tl[l + 1]);
}

// ---------------- kernel B: forward conv (fp16 mma) + LUT -> phi[px][f] fp16 ----
// Block: 128 threads. Tile 8 rows x 64 px, 32 filters. K padded 49 -> 64 (8x8).
// Parity-duplicated fp16 patch: copy1 shifted +1 half so every half2 A-load is
// 4B-aligned regardless of grp parity.
#define PSTH 80
__global__ void __launch_bounds__(128) fwd_kernel(const float* __restrict__ x)
{
    __shared__ __half patch2[2][15 * PSTH];   // 4.8 KB  (copy1 shifted +1)
    __shared__ __half wsh[32 * 72];           // 4.6 KB  [f][k], k in [0,64)

    int b  = blockIdx.z;
    int i0 = blockIdx.y * 8;
    int xt = blockIdx.x & 3;
    int fc = blockIdx.x >> 2;
    int x0 = xt * 64;
    int f0 = fc * NFC;
    int tid = threadIdx.x;

    const float* xb_ptr = x + (size_t)b * NH * NW;

    // patch: rows gi = i0-3+r, r in [0,15); cols gj = x0-3+c, c in [0,70)
    for (int tpos = tid; tpos < 15 * 70; tpos += 128) {
        int r = tpos / 70, c = tpos - r * 70;
        int gi = i0 - 3 + r;
        int gj = x0 - 3 + c;
        gi = (gi < 0) ? (-1 - gi) : ((gi >= NH) ? (2 * NH - 1 - gi) : gi);
        gj = (gj < 0) ? (-1 - gj) : ((gj >= NW) ? (2 * NW - 1 - gj) : gj);
        __half h = __float2half(xb_ptr[gi * NW + gj]);
        patch2[0][r * PSTH + c]     = h;
        patch2[1][r * PSTH + c + 1] = h;
    }
    // weights [f][k]: k = p*8+q, zero for q==7 or p==7
    for (int tpos = tid; tpos < 32 * 64; tpos += 128) {
        int f = tpos >> 6, k = tpos & 63;
        int p = k >> 3, q = k & 7;
        float v = (p < 7 && q < 7) ? d_wn[(f0 + f) * 49 + p * 7 + q] : 0.f;
        wsh[f * 72 + k] = __float2half(v);
    }
    __syncthreads();

    float g0 = d_lut[0], invstep = d_lut[2];

    int lane = tid & 31, wrp = tid >> 5;
    int lam = lane & 3;
    int grp = lane >> 2;

    // B fragments (weights) for all 4 n-tiles x 4 kk, in registers
    unsigned bfr[4][4][2];
    #pragma unroll
    for (int n = 0; n < 4; ++n)
        #pragma unroll
        for (int kk = 0; kk < 4; ++kk) {
            const __half* r = &wsh[(n * 8 + grp) * 72 + kk * 16 + 2 * lam];
            bfr[n][kk][0] = *reinterpret_cast<const unsigned*>(r);
            bfr[n][kk][1] = *reinterpret_cast<const unsigned*>(r + 8);
        }

    // parity-corrected patch base for this thread
    const __half* pb = &patch2[grp & 1][0] + (grp & 1);

    #pragma unroll 1
    for (int mt = 0; mt < 8; ++mt) {
        int py  = wrp * 2 + (mt >> 2);
        int xb2 = (mt & 3) * 16;

        float acc[4][4];
        #pragma unroll
        for (int n = 0; n < 4; ++n)
            #pragma unroll
            for (int j = 0; j < 4; ++j) acc[n][j] = 0.f;

        const __half* pp = pb + py * PSTH + xb2 + grp + 2 * lam;
        #pragma unroll
        for (int kk = 0; kk < 4; ++kk) {
            const __half* p0 = pp + 2 * kk * PSTH;
            unsigned a0 = *reinterpret_cast<const unsigned*>(p0);
            unsigned a1 = *reinterpret_cast<const unsigned*>(p0 + 8);
            unsigned a2 = *reinterpret_cast<const unsigned*>(p0 + PSTH);
            unsigned a3 = *reinterpret_cast<const unsigned*>(p0 + PSTH + 8);
            #pragma unroll
            for (int n = 0; n < 4; ++n)
                mma_f16(acc[n][0], acc[n][1], acc[n][2], acc[n][3],
                        a0, a1, a2, a3, bfr[n][kk][0], bfr[n][kk][1]);
        }

        // epilogue: LUT (clamps dead: |u| <= 0.7 << 100) + half2 stores
        int y = i0 + py;
        #pragma unroll
        for (int n = 0; n < 4; ++n) {
            int fbase = f0 + n * 8 + 2 * lam;
            const float2* tf0 = d_tab2 + (fbase)     * 1000;
            const float2* tf1 = d_tab2 + (fbase + 1) * 1000;
            #pragma unroll
            for (int h = 0; h < 2; ++h) {
                float v0 = acc[n][h * 2];
                float v1 = acc[n][h * 2 + 1];
                float pos0 = (v0 - g0) * invstep;
                float pos1 = (v1 - g0) * invstep;
                int idx0 = __float2int_rd(pos0);
                int idx1 = __float2int_rd(pos1);
                float fr0 = pos0 - (float)idx0;
                float fr1 = pos1 - (float)idx1;
                float2 tv0 = __ldg(tf0 + idx0);
                float2 tv1 = __ldg(tf1 + idx1);
                float p0 = fmaf(fr0, tv0.y - tv0.x, tv0.x);
                float p1 = fmaf(fr1, tv1.y - tv1.x, tv1.x);
                int px = x0 + xb2 + grp + h * 8;
                size_t addr = (((size_t)(b) << 16) + (y << 8) + px) * NF + fbase;
                *reinterpret_cast<__half2*>(&d_phi[addr]) = __floats2half2_rn(p0, p1);
            }
        }
    }
}

// ---------------- kernel C1: psi GEMM, fp16 mma, pipelined ----------------
#define SA_S 72
#define SB_S 72
__global__ void __launch_bounds__(128) psi_kernel()
{
    __shared__ __half sa[2][128 * SA_S];   // 2 x 18 KB
    __shared__ __half sb[56 * SB_S];       // 7.9 KB

    int b     = blockIdx.y;
    int tile0 = blockIdx.x * 4;
    int tid   = threadIdx.x;

    for (int c = tid; c < 56 * 64; c += 128) {
        int uv = c >> 6, f = c & 63;
        sb[uv * SB_S + f] = (uv < 49) ? __float2half(d_wnf[f * 49 + uv]) : __half(0.f);
    }

    #define PSI_STAGE(T, BUF)                                                   \
        {                                                                       \
            size_t srcb = (((size_t)b << 16) + (size_t)(T) * 128) * NF;         \
            for (int c = tid; c < 128 * 8; c += 128) {                          \
                int px = c >> 3, c8 = c & 7;                                    \
                cp_async16(&sa[BUF][px * SA_S + c8 * 8],                        \
                           d_phi + srcb + (size_t)px * NF + c8 * 8);            \
            }                                                                   \
            cp_commit();                                                        \
        }

    PSI_STAGE(tile0, 0)

    int lane = tid & 31, wrp = tid >> 5;
    int lam = lane & 3;
    int grp = lane >> 2;

    #pragma unroll 1
    for (int s = 0; s < 4; ++s) {
        if (s + 1 < 4) { PSI_STAGE(tile0 + s + 1, (s + 1) & 1) cp_wait1(); }
        else           { cp_wait0(); }
        __syncthreads();

        float acc[2][7][4];
        #pragma unroll
        for (int mt = 0; mt < 2; ++mt)
            #pragma unroll
            for (int n = 0; n < 7; ++n)
                #pragma unroll
                for (int j = 0; j < 4; ++j) acc[mt][n][j] = 0.f;

        const __half* sab = sa[s & 1];
        #pragma unroll
        for (int kk = 0; kk < 4; ++kk) {
            int kb = kk * 16 + 2 * lam;
            unsigned bf[7][2];
            #pragma unroll
            for (int n = 0; n < 7; ++n) {
                const __half* r = sb + (n * 8 + grp) * SB_S + kb;
                bf[n][0] = *reinterpret_cast<const unsigned*>(r);
                bf[n][1] = *reinterpret_cast<const unsigned*>(r + 8);
            }
            #pragma unroll
            for (int mt = 0; mt < 2; ++mt) {
                int mrow = (wrp * 2 + mt) * 16 + grp;
                const __half* ra = sab + mrow * SA_S + kb;
                unsigned a0 = *reinterpret_cast<const unsigned*>(ra);
                unsigned a1 = *reinterpret_cast<const unsigned*>(ra + 8 * SA_S);
                unsigned a2 = *reinterpret_cast<const unsigned*>(ra + 8);
                unsigned a3 = *reinterpret_cast<const unsigned*>(ra + 8 * SA_S + 8);
                #pragma unroll
                for (int n = 0; n < 7; ++n)
                    mma_f16(acc[mt][n][0], acc[mt][n][1], acc[mt][n][2], acc[mt][n][3],
                            a0, a1, a2, a3, bf[n][0], bf[n][1]);
            }
        }

        size_t bpx = ((size_t)b << 16) + (size_t)(tile0 + s) * 128;
        #pragma unroll
        for (int mt = 0; mt < 2; ++mt) {
            #pragma unroll
            for (int n = 0; n < 7; ++n) {
                #pragma unroll
                for (int j = 0; j < 4; ++j) {
                    int uv = n * 8 + 2 * lam + (j & 1);
                    if (uv < 49) {
                        int pl = (wrp * 2 + mt) * 16 + grp + 8 * (j >> 1);
                        d_psi[(size_t)uv * PSIPLANE + bpx + pl] =
                            __float2half(acc[mt][n][j]);
                    }
                }
            }
        }
        __syncthreads();
    }
    #undef PSI_STAGE
}

// ---------------- kernel C2: fold (fp16 psi in, fp32 g out) ----------------
__global__ void __launch_bounds__(256) fold_kernel()
{
    int t = blockIdx.x * 256 + threadIdx.x;
    if (t >= GP * GP) return;
    int b = blockIdx.y;
    int m = t / GP;
    int n = t - m * GP;

    float acc = 0.f;
    #pragma unroll
    for (int u = 0; u < 7; ++u) {
        int y = m - 6 + u;
        if ((unsigned)y < (unsigned)NH) {
            const __half* base = d_psi + (size_t)(u * 7) * PSIPLANE
                               + ((size_t)b << 16) + (y << 8);
            #pragma unroll
            for (int v = 0; v < 7; ++v) {
                int xx = n - 6 + v;
                if ((unsigned)xx < (unsigned)NW)
                    acc += __half2float(base[(size_t)v * PSIPLANE + xx]);
            }
        }
    }
    d_g[(size_t)b * GP * GP + t] = acc;
}

// ---------------- kernel D: fold borders + residual + prox ----------------
__global__ void finish_kernel(const float* __restrict__ input,
                              const float* __restrict__ noisy,
                              const float* __restrict__ a_cond,
                              float* __restrict__ out)
{
    int t = blockIdx.x * blockDim.x + threadIdx.x;
    if (t >= NB * NH * NW) return;
    int b   = t >> 16;
    int rem = t & 65535;
    int i = rem >> 8, j = rem & 255;

    const float* gb = d_g + (size_t)b * GP * GP;

    int mi[2], nj[2];
    int nm = 1, nn = 1;
    mi[0] = i + 3;
    nj[0] = j + 3;
    if (i < 3)       mi[nm++] = 2 - i;
    if (i >= NH - 3) mi[nm++] = 2 * NH + 2 - i;
    if (j < 3)       nj[nn++] = 2 - j;
    if (j >= NW - 3) nj[nn++] = 2 * NW + 2 - j;

    float r = 0.f;
    for (int a = 0; a < nm; ++a)
        for (int c = 0; c < nn; ++c)
            r += gb[mi[a] * GP + nj[c]];

    float av = a_cond[b];
    float z = input[t] - r;
    float d = z - av;
    out[t] = 0.5f * (d + sqrtf(d * d + 4.0f * av * noisy[t]));
}

// ---------------- launch ----------------
extern "C" void kernel_launch(void* const* d_in, const int* in_sizes, int n_in,
                              void* d_out, int out_size)
{
    const float* input   = (const float*)d_in[0];
    const float* noisy   = (const float*)d_in[1];
    const float* a_cond  = (const float*)d_in[2];
    const float* cw      = (const float*)d_in[3];
    const float* sf      = (const float*)d_in[4];
    const float* rw      = (const float*)d_in[5];
    const float* centers = (const float*)d_in[6];
    const float* grid    = (const float*)d_in[7];
    float* out = (float*)d_out;

    prep_weights<<<1, 64>>>(cw, sf, grid);
    prep_table<<<NF, 128>>>(rw, centers, grid);
    fwd_kernel<<<dim3(8, 32, NB), 128>>>(input);
    psi_kernel<<<dim3(128, NB), 128>>>();
    fold_kernel<<<dim3((GP * GP + 255) / 256, NB), 256>>>();
    finish_kernel<<<(NB * NH * NW + 255) / 256, 256>>>(input, noisy, a_cond, out);
}